// round 6
// baseline (speedup 1.0000x reference)
#include <cuda_runtime.h>

// SigmoidFlow: xnew = logit( sum_k softmax(wl)_k * sigmoid(a_k x + b_k) ), plus
// per-row logdet accumulation. All log-domain terms collapsed to linear domain:
//   logj = log( sum_k e_k * a_k * s_k(1-s_k) ) - log( sum_k e_k ),  e_k = exp(wl_k)
// with s(1-s) = u*r^2, u = exp(-|pre|), r = 1/(1+u)  (valid for both signs).

#define NDIM 16
#define DELTA_F 1e-6f
// log(1 - 1e-6)
#define LOG1MDELTA (-1.0000005e-6f)

__global__ __launch_bounds__(512, 1)
void sigmoid_flow_kernel(const float* __restrict__ x,
                         const float* __restrict__ logdet_in,
                         const float* __restrict__ dsp,
                         float* __restrict__ out_xnew,
                         float* __restrict__ out_logdet,
                         int D)
{
    const int b = blockIdx.x;
    const int d = threadIdx.x;
    const long long idx = (long long)b * D + d;

    // ---- front-batched loads: 12x LDG.128 (48 contiguous floats) + x scalar ----
    const float4* __restrict__ p =
        reinterpret_cast<const float4*>(dsp + idx * (3 * NDIM));
    float4 va[4], vb[4], vw[4];
#pragma unroll
    for (int i = 0; i < 4; i++) va[i] = p[i];
#pragma unroll
    for (int i = 0; i < 4; i++) vb[i] = p[4 + i];
#pragma unroll
    for (int i = 0; i < 4; i++) vw[i] = p[8 + i];
    const float xv = x[idx];

    float aL[NDIM], bL[NDIM], wL[NDIM];
#pragma unroll
    for (int i = 0; i < 4; i++) {
        aL[4 * i + 0] = va[i].x; aL[4 * i + 1] = va[i].y;
        aL[4 * i + 2] = va[i].z; aL[4 * i + 3] = va[i].w;
        bL[4 * i + 0] = vb[i].x; bL[4 * i + 1] = vb[i].y;
        bL[4 * i + 2] = vb[i].z; bL[4 * i + 3] = vb[i].w;
        wL[4 * i + 0] = vw[i].x; wL[4 * i + 1] = vw[i].y;
        wL[4 * i + 2] = vw[i].z; wL[4 * i + 3] = vw[i].w;
    }

    // ---- fused per-k math, all linear domain ----
    float Se = 0.0f;   // sum_k e_k
    float S1 = 0.0f;   // sum_k e_k * s_k
    float S2 = 0.0f;   // sum_k e_k * a_k * s_k(1-s_k)
#pragma unroll
    for (int k = 0; k < NDIM; k++) {
        // a = softplus(z), numerically stable
        const float z = aL[k];
        const float t = __expf(-fabsf(z));
        const float a = fmaxf(z, 0.0f) + __logf(1.0f + t);

        // pre_sigm, sigmoid via shared exp(-|pre|)
        const float pre = fmaf(a, xv, bL[k]);
        const float u = __expf(-fabsf(pre));
        const float r = __fdividef(1.0f, 1.0f + u);
        const float s = (pre > 0.0f) ? r : u * r;   // sigmoid(pre)
        const float ss = u * r * r;                 // sigmoid(pre)*sigmoid(-pre)

        // unnormalized softmax weight (wl ~ N(0,1): no max-shift needed in f32)
        const float e = __expf(wL[k]);

        Se += e;
        S1 = fmaf(e, s, S1);
        S2 = fmaf(e * a, ss, S2);
    }

    // ---- per-element epilogue ----
    const float x_pre = S1 * __fdividef(1.0f, Se);
    const float xpc = fmaf(x_pre, 1.0f - DELTA_F, 0.5f * DELTA_F);
    const float lx  = __logf(xpc);
    const float l1x = __logf(1.0f - xpc);
    out_xnew[idx] = lx - l1x;

    const float logj = __logf(S2) - __logf(Se);
    float ld = logj + LOG1MDELTA - lx - l1x;

    // ---- deterministic block reduction for logdet (no float atomics) ----
    const int lane = d & 31;
    const int warp = d >> 5;
#pragma unroll
    for (int o = 16; o > 0; o >>= 1)
        ld += __shfl_xor_sync(0xffffffffu, ld, o);

    __shared__ float sred[32];
    if (lane == 0) sred[warp] = ld;
    __syncthreads();

    if (warp == 0) {
        const int nwarps = blockDim.x >> 5;
        float v = (lane < nwarps) ? sred[lane] : 0.0f;
#pragma unroll
        for (int o = 16; o > 0; o >>= 1)
            v += __shfl_xor_sync(0xffffffffu, v, o);
        if (lane == 0)
            out_logdet[b] = v + logdet_in[b];
    }
}

extern "C" void kernel_launch(void* const* d_in, const int* in_sizes, int n_in,
                              void* d_out, int out_size)
{
    const float* x         = (const float*)d_in[0];   // (B, D)
    const float* logdet_in = (const float*)d_in[1];   // (B,)
    const float* dsp       = (const float*)d_in[2];   // (B, D, 3*NDIM)

    const int B = in_sizes[1];
    const int D = in_sizes[0] / B;   // 512

    float* out_xnew   = (float*)d_out;                      // (B, D)
    float* out_logdet = (float*)d_out + (size_t)B * D;      // (B,)

    sigmoid_flow_kernel<<<B, D>>>(x, logdet_in, dsp, out_xnew, out_logdet, D);
}

// round 7
// speedup vs baseline: 1.4013x; 1.4013x over previous
#include <cuda_runtime.h>

// SigmoidFlow: xnew = logit( sum_k softmax(wl)_k * sigmoid(a_k x + b_k) ), plus
// per-row logdet accumulation. All log-domain terms collapsed to linear domain:
//   logj = log( sum_k e_k * a_k * s_k(1-s_k) ) - log( sum_k e_k ),  e_k = exp(wl_k)
// with s(1-s) = u*r^2, u = exp(-|pre|), r = 1/(1+u)  (valid for both signs).
//
// R6: grouped loads (4 k's at a time) + __launch_bounds__(512,2) so regs <= 64
// and 2 CTAs/SM coexist -> 32 warps/SM for DRAM latency hiding.

#define NDIM 16
#define DELTA_F 1e-6f
// log(1 - 1e-6)
#define LOG1MDELTA (-1.0000005e-6f)

__global__ __launch_bounds__(512, 2)
void sigmoid_flow_kernel(const float* __restrict__ x,
                         const float* __restrict__ logdet_in,
                         const float* __restrict__ dsp,
                         float* __restrict__ out_xnew,
                         float* __restrict__ out_logdet,
                         int D)
{
    const int b = blockIdx.x;
    const int d = threadIdx.x;
    const long long idx = (long long)b * D + d;

    const float4* __restrict__ p =
        reinterpret_cast<const float4*>(dsp + idx * (3 * NDIM));
    const float xv = x[idx];

    float Se = 0.0f;   // sum_k e_k
    float S1 = 0.0f;   // sum_k e_k * s_k
    float S2 = 0.0f;   // sum_k e_k * a_k * s_k(1-s_k)

#pragma unroll
    for (int i = 0; i < 4; i++) {
        // group i covers k = 4i .. 4i+3
        const float4 va = p[i];
        const float4 vb = p[4 + i];
        const float4 vw = p[8 + i];

        const float zs[4] = {va.x, va.y, va.z, va.w};
        const float bs[4] = {vb.x, vb.y, vb.z, vb.w};
        const float ws[4] = {vw.x, vw.y, vw.z, vw.w};

#pragma unroll
        for (int j = 0; j < 4; j++) {
            // a = softplus(z), numerically stable
            const float z = zs[j];
            const float t = __expf(-fabsf(z));
            const float a = fmaxf(z, 0.0f) + __logf(1.0f + t);

            // pre_sigm, sigmoid via shared exp(-|pre|)
            const float pre = fmaf(a, xv, bs[j]);
            const float u = __expf(-fabsf(pre));
            const float r = __fdividef(1.0f, 1.0f + u);
            const float s = (pre > 0.0f) ? r : u * r;   // sigmoid(pre)
            const float ss = u * r * r;                 // sigm(pre)*sigm(-pre)

            // unnormalized softmax weight (wl ~ N(0,1): safe without max-shift)
            const float e = __expf(ws[j]);

            Se += e;
            S1 = fmaf(e, s, S1);
            S2 = fmaf(e * a, ss, S2);
        }
    }

    // ---- per-element epilogue ----
    const float invSe = __fdividef(1.0f, Se);
    const float x_pre = S1 * invSe;
    const float xpc = fmaf(x_pre, 1.0f - DELTA_F, 0.5f * DELTA_F);
    const float lx  = __logf(xpc);
    const float l1x = __logf(1.0f - xpc);
    out_xnew[idx] = lx - l1x;

    const float logj = __logf(S2 * invSe);   // log(S2) - log(Se), one MUFU
    float ld = logj + LOG1MDELTA - lx - l1x;

    // ---- deterministic block reduction for logdet (no float atomics) ----
    const int lane = d & 31;
    const int warp = d >> 5;
#pragma unroll
    for (int o = 16; o > 0; o >>= 1)
        ld += __shfl_xor_sync(0xffffffffu, ld, o);

    __shared__ float sred[32];
    if (lane == 0) sred[warp] = ld;
    __syncthreads();

    if (warp == 0) {
        const int nwarps = blockDim.x >> 5;
        float v = (lane < nwarps) ? sred[lane] : 0.0f;
#pragma unroll
        for (int o = 16; o > 0; o >>= 1)
            v += __shfl_xor_sync(0xffffffffu, v, o);
        if (lane == 0)
            out_logdet[b] = v + logdet_in[b];
    }
}

extern "C" void kernel_launch(void* const* d_in, const int* in_sizes, int n_in,
                              void* d_out, int out_size)
{
    const float* x         = (const float*)d_in[0];   // (B, D)
    const float* logdet_in = (const float*)d_in[1];   // (B,)
    const float* dsp       = (const float*)d_in[2];   // (B, D, 3*NDIM)

    const int B = in_sizes[1];
    const int D = in_sizes[0] / B;   // 512

    float* out_xnew   = (float*)d_out;                      // (B, D)
    float* out_logdet = (float*)d_out + (size_t)B * D;      // (B,)

    sigmoid_flow_kernel<<<B, D>>>(x, logdet_in, dsp, out_xnew, out_logdet, D);
}

// round 9
// speedup vs baseline: 1.6013x; 1.1427x over previous
#include <cuda_runtime.h>

// SigmoidFlow, quad-split: 4 threads cooperate on one (b,d) element, each
// handling 4 of the 16 mixture components. This makes global loads
// quasi-coalesced (64B-contiguous chunks per quad instead of 192B-strided
// lanes), cutting L1tex wavefronts ~2.7x, and drops register pressure so
// 3 CTAs/SM fit (48 warps).
//
// Math (linear-domain collapse of the reference):
//   logj = log( sum_k e_k * a_k * s_k(1-s_k) ) - log( sum_k e_k ), e_k=exp(wl_k)
//   s(1-s) = u*r^2, u = exp(-|pre|), r = 1/(1+u)  (both signs).

#define NDIM 16
#define DELTA_F 1e-6f
#define LOG1MDELTA (-1.0000005e-6f)   // log(1 - 1e-6)

__global__ __launch_bounds__(512, 3)
void sigmoid_flow_kernel(const float* __restrict__ x,
                         const float* __restrict__ logdet_in,
                         const float* __restrict__ dsp,
                         float* __restrict__ out_xnew,
                         float* __restrict__ out_logdet,
                         int D)
{
    const int b = blockIdx.x;
    const int t = threadIdx.x;
    const int q = t >> 2;     // element slot within pass (0..127)
    const int c = t & 3;      // which float4 chunk of the element (0..3)

    const float4* __restrict__ dsp4 = reinterpret_cast<const float4*>(dsp);

    float ldsum = 0.0f;       // per-thread logdet accumulator (lane c==0 only)

    // D=512: 4 passes of 128 elements per 512-thread block
#pragma unroll 4
    for (int d0 = 0; d0 < D; d0 += 128) {
        const int e = b * D + d0 + q;
        const long long rec = (long long)e * 12;   // 12 float4s per record

        // quasi-coalesced: quad lanes read 4 consecutive float4s (64B)
        const float4 va = dsp4[rec + c];
        const float4 vb = dsp4[rec + 4 + c];
        const float4 vw = dsp4[rec + 8 + c];
        const float xv = x[e];                      // broadcast within quad

        const float zs[4] = {va.x, va.y, va.z, va.w};
        const float bs[4] = {vb.x, vb.y, vb.z, vb.w};
        const float ws[4] = {vw.x, vw.y, vw.z, vw.w};

        float Se = 0.0f, S1 = 0.0f, S2 = 0.0f;
#pragma unroll
        for (int j = 0; j < 4; j++) {
            // a = softplus(z), numerically stable
            const float z = zs[j];
            const float tt = __expf(-fabsf(z));
            const float a = fmaxf(z, 0.0f) + __logf(1.0f + tt);

            // sigmoid terms via shared exp(-|pre|)
            const float pre = fmaf(a, xv, bs[j]);
            const float u = __expf(-fabsf(pre));
            const float r = __fdividef(1.0f, 1.0f + u);
            const float s = (pre > 0.0f) ? r : u * r;  // sigmoid(pre)
            const float ss = u * r * r;                // sigm(pre)*sigm(-pre)

            const float ek = __expf(ws[j]);            // unnormalized softmax

            Se += ek;
            S1 = fmaf(ek, s, S1);
            S2 = fmaf(ek * a, ss, S2);
        }

        // reduce the three sums across the quad (lanes c, c^1, c^2, c^3)
        Se += __shfl_xor_sync(0xffffffffu, Se, 1);
        Se += __shfl_xor_sync(0xffffffffu, Se, 2);
        S1 += __shfl_xor_sync(0xffffffffu, S1, 1);
        S1 += __shfl_xor_sync(0xffffffffu, S1, 2);
        S2 += __shfl_xor_sync(0xffffffffu, S2, 1);
        S2 += __shfl_xor_sync(0xffffffffu, S2, 2);

        // epilogue: computed by all quad lanes (no divergence), stored by c==0
        const float invSe = __fdividef(1.0f, Se);
        const float x_pre = S1 * invSe;
        const float xpc = fmaf(x_pre, 1.0f - DELTA_F, 0.5f * DELTA_F);
        const float lx  = __logf(xpc);
        const float l1x = __logf(1.0f - xpc);
        const float logj = __logf(S2 * invSe);

        if (c == 0) {
            out_xnew[e] = lx - l1x;
            ldsum += logj + LOG1MDELTA - lx - l1x;
        }
    }

    // ---- deterministic block reduction for logdet (no float atomics) ----
    const int lane = t & 31;
    const int warp = t >> 5;
#pragma unroll
    for (int o = 16; o > 0; o >>= 1)
        ldsum += __shfl_xor_sync(0xffffffffu, ldsum, o);

    __shared__ float sred[16];
    if (lane == 0) sred[warp] = ldsum;
    __syncthreads();

    if (warp == 0) {
        float v = (lane < 16) ? sred[lane] : 0.0f;
#pragma unroll
        for (int o = 16; o > 0; o >>= 1)
            v += __shfl_xor_sync(0xffffffffu, v, o);
        if (lane == 0)
            out_logdet[b] = v + logdet_in[b];
    }
}

extern "C" void kernel_launch(void* const* d_in, const int* in_sizes, int n_in,
                              void* d_out, int out_size)
{
    const float* x         = (const float*)d_in[0];   // (B, D)
    const float* logdet_in = (const float*)d_in[1];   // (B,)
    const float* dsp       = (const float*)d_in[2];   // (B, D, 3*NDIM)

    const int B = in_sizes[1];
    const int D = in_sizes[0] / B;   // 512

    float* out_xnew   = (float*)d_out;                      // (B, D)
    float* out_logdet = (float*)d_out + (size_t)B * D;      // (B,)

    sigmoid_flow_kernel<<<B, 512>>>(x, logdet_in, dsp, out_xnew, out_logdet, D);
}